// round 13
// baseline (speedup 1.0000x reference)
#include <cuda_runtime.h>
#include <cuda_bf16.h>
#include <float.h>

#define UE   10000
#define HD   128
#define KSEL 32
#define FULLM 0xffffffffu

// ---------------- scratch (device globals; no runtime allocation) ----------
__device__ int   g_umap[UE * KSEL];
__device__ int   g_smap[UE * KSEL];
__device__ float g_cu[UE * HD];          // conv output per user
__device__ float g_ds[UE * HD];          // conv output per service
// projections: [src 0=a(u),1=c(u),2=b(s),3=d(s)][entity][0:128 wf-proj | 128:256 wi-proj]
__device__ float g_proj[4 * UE * 256];
// packed selected features per batch element (row-major 16384 x 512)
__device__ float g_x[16384 * 512];
// dedup flags + compact used-entity lists; counters live in the tail
// [0:UE) user flags, [UE:2UE) service flags, [2UE]=user count, [2UE+1]=service count
__device__ int g_flagi[2 * UE + 2];
__device__ int g_ulist[UE];
__device__ int g_slist[UE];
// pre-transposed weights: [z][cp2][h] as float4 = W[h][4cp2 .. 4cp2+3]
__device__ float4 g_wT[2 * 32 * 128];

typedef unsigned long long ull;

__device__ __forceinline__ void fma2(ull& d, ull a, ull b) {
    asm("fma.rn.f32x2 %0, %1, %2, %0;" : "+l"(d) : "l"(a), "l"(b));
}
__device__ __forceinline__ ull dupf(float x) {
    unsigned xi = __float_as_uint(x);
    ull r; asm("mov.b64 %0, {%1, %1};" : "=l"(r) : "r"(xi));
    return r;
}
__device__ __forceinline__ float hsum(ull a) {
    unsigned lo, hi;
    asm("mov.b64 {%0, %1}, %2;" : "=r"(lo), "=r"(hi) : "l"(a));
    return __uint_as_float(lo) + __uint_as_float(hi);
}

// ---------------------------------------------------------------------------
// Kernel 0: fused prep. Blocks 0-31: transpose W into g_wT. Blocks 32+:
// mark used entities + build compact lists (g_flagi zeroed by memset).
// ---------------------------------------------------------------------------
__global__ void prepmark_kernel(const float* __restrict__ wf,
                                const float* __restrict__ wi,
                                const int* __restrict__ data, int Bn) {
    int b = blockIdx.x, tid = threadIdx.x;
    if (b < 32) {
        int idx = b * 256 + tid;               // < 8192
        int z   = idx >> 12;
        int cp2 = (idx >> 7) & 31;
        int h   = idx & 127;
        const float* W = z ? wi : wf;
        g_wT[idx] = *(const float4*)(W + h * HD + cp2 * 4);
    } else {
        int i = (b - 32) * 256 + tid;
        if (i >= Bn) return;
        int uid = data[i * 3 + 1];
        int sid = data[i * 3 + 2];
        if (atomicExch(&g_flagi[uid], 1) == 0) {
            int p = atomicAdd(&g_flagi[2 * UE], 1);
            g_ulist[p] = uid;
        }
        if (atomicExch(&g_flagi[UE + sid], 1) == 0) {
            int p = atomicAdd(&g_flagi[2 * UE + 1], 1);
            g_slist[p] = sid;
        }
    }
}

// ---------------------------------------------------------------------------
// Kernel A v5: per-row top-32, TWO warps per row (one per 5000-elem half).
// Each warp: MLP=4 loads, gate ballot per 128-float sub-tile, per-component
// candidate ballots (1 shfl/candidate, 9-issue insert, thr deferred per
// component). Halves merged by the sorted-merge lemma:
//   top32(A ∪ B) = { max(A[i], B[31-i]) },  tie -> A (lower-index half).
// Then bitonic index-sort ascending. 4 rows per 256-thread CTA.
// ---------------------------------------------------------------------------
__global__ void __launch_bounds__(256) topk_kernel(
        const float* __restrict__ user_sim,
        const float* __restrict__ service_sim) {
    __shared__ float sv[4][32];
    __shared__ int   si[4][32];

    int tid  = threadIdx.x;
    int lane = tid & 31;
    int warp = tid >> 5;                 // 0..7
    int p    = warp >> 1;                // pair slot 0..3
    int half = warp & 1;                 // 0 = front half, 1 = back half
    int rowIdx = blockIdx.x * 4 + p;     // 0..19999

    const float* row;
    int* outp;
    if (rowIdx < UE) {
        if (rowIdx >= g_flagi[2 * UE]) return;
        int rid = g_ulist[rowIdx];
        row = user_sim + (size_t)rid * UE;
        outp = g_umap + rid * KSEL;
    } else {
        int sg = rowIdx - UE;
        if (sg >= g_flagi[2 * UE + 1]) return;
        int rid = g_slist[sg];
        row = service_sim + (size_t)rid * UE;
        outp = g_smap + rid * KSEL;
    }

    const float4* row4 = (const float4*)row;
    const int start = half ? 1250 : 0;   // float4 index
    const int limit = half ? 2500 : 1250;

    float lv = -FLT_MAX;   // local list value at rank = lane (descending)
    int   li = 0;
    float thr = -FLT_MAX;  // rank-31 value, refreshed per component block

    #pragma unroll 1
    for (int it = 0; it < 10; it++) {    // 10 x 512 floats per warp-half
        int i0 = start + it * 128 + lane;
        float4 f[4];
        #pragma unroll
        for (int k = 0; k < 4; k++) {
            int i = i0 + 32 * k;
            if (i < limit) f[k] = __ldcs(row4 + i);
            else           f[k] = make_float4(-FLT_MAX, -FLT_MAX, -FLT_MAX, -FLT_MAX);
        }
        #pragma unroll
        for (int k = 0; k < 4; k++) {
            float m = fmaxf(fmaxf(f[k].x, f[k].y), fmaxf(f[k].z, f[k].w));
            if (__ballot_sync(FULLM, m > thr) == 0) continue;  // warp-uniform
            int base = (start + it * 128 + 32 * k) * 4;
            float comps[4] = {f[k].x, f[k].y, f[k].z, f[k].w};
            #pragma unroll
            for (int t = 0; t < 4; t++) {
                unsigned ct = __ballot_sync(FULLM, comps[t] > thr);
                while (ct) {
                    int src = __ffs(ct) - 1;
                    ct &= ct - 1;
                    float v = __shfl_sync(FULLM, comps[t], src);
                    // sorted insert vs LIVE list; stale-thr candidates give
                    // pos==32 -> no lane matches -> rank-correct no-op
                    unsigned ge = __ballot_sync(FULLM, lv >= v);
                    int pos = __popc(ge);
                    float slv = __shfl_up_sync(FULLM, lv, 1);
                    int   sli = __shfl_up_sync(FULLM, li, 1);
                    if (lane > pos)       { lv = slv; li = sli; }
                    else if (lane == pos) { lv = v;   li = base + src * 4 + t; }
                }
                thr = __shfl_sync(FULLM, lv, 31);   // refresh once per component
            }
        }
    }

    // exchange: back-half warp publishes its sorted list
    if (half) { sv[p][lane] = lv; si[p][lane] = li; }
    __syncthreads();    // exited warps don't block (Volta+ semantics)
    if (half) return;

    // merge lemma: C[lane] = max(A[lane], B[31-lane]); tie -> A (lower idx)
    {
        float pv = sv[p][31 - lane];
        int   pi = si[p][31 - lane];
        if (pv > lv) { lv = pv; li = pi; }
    }

    // bitonic sort of the 32 merged indices ascending
    #pragma unroll
    for (int k = 2; k <= 32; k <<= 1) {
        #pragma unroll
        for (int j = k >> 1; j > 0; j >>= 1) {
            int partner = __shfl_xor_sync(FULLM, li, j);
            bool up    = ((lane & k) == 0);
            bool small = ((lane & j) == 0);
            int mn = min(li, partner), mx = max(li, partner);
            li = (up == small) ? mn : mx;
        }
    }
    outp[lane] = li;
}

// ---------------------------------------------------------------------------
// Kernel B: per-entity 32x7 conv over gathered neighbor embeddings.
// One warp per used entity (dense via compact lists).  (R8-proven version.)
// ---------------------------------------------------------------------------
__global__ void conv_kernel(const float* __restrict__ user_emb,
                            const float* __restrict__ service_emb,
                            const float* __restrict__ cnn_w,
                            const float* __restrict__ cnn_b,
                            const float* __restrict__ scnn_w,
                            const float* __restrict__ scnn_b) {
    __shared__ float sw[224];
    __shared__ float sb;
    int e0 = blockIdx.x * 8;           // 8 warps per CTA; sides split at CTA 1250
    bool user = (e0 < UE);
    const float* emb  = user ? user_emb : service_emb;
    const int*   map  = user ? g_umap   : g_smap;
    float*       outc = user ? g_cu     : g_ds;
    const float* wsrc = user ? cnn_w    : scnn_w;
    if (threadIdx.x < 224) sw[threadIdx.x] = wsrc[threadIdx.x];
    if (threadIdx.x == 0)  sb = (user ? cnn_b : scnn_b)[0];
    __syncthreads();

    int warp = threadIdx.x >> 5, lane = threadIdx.x & 31;
    int widx = e0 + warp;
    int el;
    if (user) {
        if (widx >= g_flagi[2 * UE]) return;
        el = g_ulist[widx];
    } else {
        int sg = widx - UE;
        if (sg >= g_flagi[2 * UE + 1]) return;
        el = g_slist[sg];
    }

    int mk = map[el * KSEL + lane];    // lane holds neighbor index #lane

    float m[7][4];
    #pragma unroll
    for (int t = 0; t < 7; t++)
        m[t][0] = m[t][1] = m[t][2] = m[t][3] = 0.f;

    for (int k = 0; k < 32; k++) {
        int nb = __shfl_sync(FULLM, mk, k);
        float4 x = *(const float4*)(emb + (size_t)nb * HD + lane * 4);
        #pragma unroll
        for (int t = 0; t < 7; t++) {
            float w = sw[k * 7 + t];
            m[t][0] = fmaf(x.x, w, m[t][0]);
            m[t][1] = fmaf(x.y, w, m[t][1]);
            m[t][2] = fmaf(x.z, w, m[t][2]);
            m[t][3] = fmaf(x.w, w, m[t][3]);
        }
    }

    float acc[4] = {sb, sb, sb, sb};
    #pragma unroll
    for (int t = 0; t < 7; t++) {
        float up[4], dn[4];
        #pragma unroll
        for (int j = 0; j < 4; j++) up[j] = __shfl_up_sync(FULLM, m[t][j], 1);
        #pragma unroll
        for (int j = 0; j < 4; j++) dn[j] = __shfl_down_sync(FULLM, m[t][j], 1);
        if (lane == 0)  { up[0] = up[1] = up[2] = up[3] = 0.f; }
        if (lane == 31) { dn[0] = dn[1] = dn[2] = dn[3] = 0.f; }
        const int d = t - 3;
        #pragma unroll
        for (int i = 0; i < 4; i++) {
            const int q = i + d;
            float v = (q < 0) ? up[q + 4] : ((q > 3) ? dn[q - 4] : m[t][q]);
            acc[i] += v;
        }
    }
    float4 o = make_float4(acc[0], acc[1], acc[2], acc[3]);
    *(float4*)(outc + (size_t)el * HD + lane * 4) = o;
}

// ---------------------------------------------------------------------------
// Kernel C v2: projection GEMM over USED entities only.
// Tile: 32 rows x 128 h per CTA (256 thr); warp = 8 rows x 64 h.
// W read via coalesced LDG.128 from pre-transposed g_wT (L1-resident);
// X broadcast LDS.128 from 16 KB smem tile. acc in f32x2. 4 CTAs/SM target.
// ---------------------------------------------------------------------------
__global__ void __launch_bounds__(256, 4) proj_kernel(
        const float* __restrict__ user_emb,
        const float* __restrict__ service_emb) {
    __shared__ float sX[32 * 128];    // 16 KB
    __shared__ int   sRid[32];

    int srcsel = blockIdx.y;          // 0=a(u emb),1=c(u conv),2=b(s emb),3=d(s conv)
    int z = blockIdx.z;               // 0 -> wf, 1 -> wi
    bool userSide = (srcsel < 2);
    int cnt = userSide ? g_flagi[2 * UE] : g_flagi[2 * UE + 1];
    int row0 = blockIdx.x * 32;
    if (row0 >= cnt) return;
    const int* list = userSide ? g_ulist : g_slist;
    const float* X;
    switch (srcsel) {
        case 0:  X = user_emb;    break;
        case 1:  X = g_cu;        break;
        case 2:  X = service_emb; break;
        default: X = g_ds;        break;
    }

    int tid = threadIdx.x;
    if (tid < 32) sRid[tid] = (row0 + tid < cnt) ? list[row0 + tid] : -1;
    __syncthreads();   // sRid visible for staging below

    // stage 32 rows x 128 c (gathered); zero-fill beyond count
    for (int idx = tid; idx < 1024; idx += 256) {
        int r = idx >> 5, c4 = idx & 31;
        int eid = sRid[r];
        float4 v = (eid >= 0) ? *(const float4*)(X + (size_t)eid * HD + c4 * 4)
                              : make_float4(0.f, 0.f, 0.f, 0.f);
        *(float4*)(sX + r * HD + c4 * 4) = v;
    }
    __syncthreads();

    int lane = tid & 31, warp = tid >> 5;
    int rg   = warp & 3;              // row group: rows rg*8 .. rg*8+7
    int hcol = warp >> 2;             // h block: hcol*64 + {0,32} + lane
    const float* xbase = sX + rg * 8 * HD;
    const float4* wbase = g_wT + (z * 32 * 128) + hcol * 64 + lane;

    ull acc[8][2] = {};

    #pragma unroll 4
    for (int cp2 = 0; cp2 < 32; cp2++) {
        float4 w0f = __ldg(wbase + cp2 * 128);
        float4 w1f = __ldg(wbase + cp2 * 128 + 32);
        ull w0x, w0y, w1x, w1y;
        asm("mov.b64 %0, {%1, %2};" : "=l"(w0x) : "f"(w0f.x), "f"(w0f.y));
        asm("mov.b64 %0, {%1, %2};" : "=l"(w0y) : "f"(w0f.z), "f"(w0f.w));
        asm("mov.b64 %0, {%1, %2};" : "=l"(w1x) : "f"(w1f.x), "f"(w1f.y));
        asm("mov.b64 %0, {%1, %2};" : "=l"(w1y) : "f"(w1f.z), "f"(w1f.w));
        #pragma unroll
        for (int i = 0; i < 8; i++) {
            const ulonglong2 x = *(const ulonglong2*)(xbase + i * HD + cp2 * 4);
            fma2(acc[i][0], x.x, w0x);
            fma2(acc[i][0], x.y, w0y);
            fma2(acc[i][1], x.x, w1x);
            fma2(acc[i][1], x.y, w1y);
        }
    }

    #pragma unroll
    for (int i = 0; i < 8; i++) {
        int eid = sRid[rg * 8 + i];
        if (eid >= 0) {
            float* dst = g_proj + (size_t)(srcsel * UE + eid) * 256 + z * 128
                       + hcol * 64 + lane;
            dst[0]  = hsum(acc[i][0]);
            dst[32] = hsum(acc[i][1]);
        }
    }
}

// ---------------------------------------------------------------------------
// Kernel D1: per-batch-element pairs + sigmoid gate + top4-by-norm; writes
// the packed 512-float selected vector to g_x. One warp per element.
// ---------------------------------------------------------------------------
__device__ __forceinline__ float pair_compute(float4 fx, float4 fy,
                                              float4 pxf, float4 pyf,
                                              float4 pxi, float4 pyi,
                                              float4 vbf, float4 vbi,
                                              float* dst, int lane) {
    float s[4]  = {fx.x + fy.x, fx.y + fy.y, fx.z + fy.z, fx.w + fy.w};
    float zf[4] = {pxf.x + pyf.x + vbf.x, pxf.y + pyf.y + vbf.y,
                   pxf.z + pyf.z + vbf.z, pxf.w + pyf.w + vbf.w};
    float zi[4] = {pxi.x + pyi.x + vbi.x, pxi.y + pyi.y + vbi.y,
                   pxi.z + pyi.z + vbi.z, pxi.w + pyi.w + vbi.w};
    float tv[4];
    float n2 = 0.f;
    #pragma unroll
    for (int c = 0; c < 4; c++) {
        float f = 1.f / (1.f + __expf(-zf[c]));
        float v = fmaf(f, zi[c] - s[c], s[c]);   // f*t + (1-f)*s
        v = fmaxf(v, 0.f);
        tv[c] = v;
        n2 = fmaf(v, v, n2);
    }
    *(float4*)(dst + lane * 4) = make_float4(tv[0], tv[1], tv[2], tv[3]);
    #pragma unroll
    for (int o = 16; o > 0; o >>= 1) n2 += __shfl_xor_sync(FULLM, n2, o);
    return n2;
}

__global__ void __launch_bounds__(256) pack_kernel(
        const int* __restrict__ data,
        const float* __restrict__ user_emb,
        const float* __restrict__ service_emb,
        const float* __restrict__ bi,
        const float* __restrict__ bf,
        int Bn) {
    __shared__ float wbuf[8 * 768];   // 8 warps * 6 pairs * 128

    int tid = threadIdx.x;
    int warp = tid >> 5, lane = tid & 31;
    int b = blockIdx.x * 8 + warp;
    if (b >= Bn) return;
    float* mybuf = wbuf + warp * 768;

    int uid = data[b * 3 + 1];
    int sid = data[b * 3 + 2];

    float4 fa  = *(const float4*)(user_emb    + (size_t)uid * HD + lane * 4);
    float4 fb  = *(const float4*)(service_emb + (size_t)sid * HD + lane * 4);
    float4 fc4 = *(const float4*)(g_cu + (size_t)uid * HD + lane * 4);
    float4 fd  = *(const float4*)(g_ds + (size_t)sid * HD + lane * 4);

    const float* pA = g_proj + (size_t)(0 * UE + uid) * 256;
    const float* pC = g_proj + (size_t)(1 * UE + uid) * 256;
    const float* pB = g_proj + (size_t)(2 * UE + sid) * 256;
    const float* pD = g_proj + (size_t)(3 * UE + sid) * 256;
    float4 aF = *(const float4*)(pA + lane * 4);
    float4 aI = *(const float4*)(pA + 128 + lane * 4);
    float4 cF = *(const float4*)(pC + lane * 4);
    float4 cI = *(const float4*)(pC + 128 + lane * 4);
    float4 bF = *(const float4*)(pB + lane * 4);
    float4 bI = *(const float4*)(pB + 128 + lane * 4);
    float4 dF = *(const float4*)(pD + lane * 4);
    float4 dI = *(const float4*)(pD + 128 + lane * 4);

    float4 vbf = *(const float4*)(bf + lane * 4);
    float4 vbi = *(const float4*)(bi + lane * 4);

    float norms[6];
    norms[0] = pair_compute(fa,  fb,  aF, bF, aI, bI, vbf, vbi, mybuf + 0 * 128, lane); // a+b
    norms[1] = pair_compute(fa,  fc4, aF, cF, aI, cI, vbf, vbi, mybuf + 1 * 128, lane); // a+c
    norms[2] = pair_compute(fa,  fd,  aF, dF, aI, dI, vbf, vbi, mybuf + 2 * 128, lane); // a+d
    norms[3] = pair_compute(fb,  fc4, bF, cF, bI, cI, vbf, vbi, mybuf + 3 * 128, lane); // b+c
    norms[4] = pair_compute(fb,  fd,  bF, dF, bI, dI, vbf, vbi, mybuf + 4 * 128, lane); // b+d
    norms[5] = pair_compute(fc4, fd,  cF, dF, cI, dI, vbf, vbi, mybuf + 5 * 128, lane); // c+d

    // top-4 by norm (desc), ties -> lower index (strict >, ascending scan)
    int ord[4];
    unsigned usedm = 0;
    #pragma unroll
    for (int r = 0; r < 4; r++) {
        int best = 0; float bv = -1.f;
        #pragma unroll
        for (int p = 0; p < 6; p++) {
            bool ok = !((usedm >> p) & 1u) && (norms[p] > bv);
            if (ok) { bv = norms[p]; best = p; }
        }
        ord[r] = best;
        usedm |= (1u << best);
    }
    __syncwarp();

    float* xdst = g_x + (size_t)b * 512;
    #pragma unroll
    for (int r = 0; r < 4; r++) {
        float4 v = *(const float4*)(mybuf + ord[r] * 128 + lane * 4);
        *(float4*)(xdst + r * 128 + lane * 4) = v;
    }
}

// ---------------------------------------------------------------------------
// Kernel D2: fc GEMM. out[16384 x 64] = g_x[16384 x 512] @ fc_w.T + fc_b.
// ---------------------------------------------------------------------------
__global__ void __launch_bounds__(256) fc_kernel(
        const float* __restrict__ fc_w,
        const float* __restrict__ fc_b,
        float* __restrict__ out, int Bn) {
    __shared__ ull sW[64 * 64];   // 32 KB: chunk of 64 c-pairs x 64 h

    int tid = threadIdx.x, lane = tid & 31, warp = tid >> 5;
    int row0 = blockIdx.x * 32 + warp * 4;

    ull acc[4][2] = {};

    #pragma unroll 1
    for (int kc = 0; kc < 4; kc++) {
        __syncthreads();
        for (int idx = tid; idx < 4096; idx += 256) {
            int cp = idx >> 6, h = idx & 63;
            sW[cp * 64 + h] = *(const ull*)(fc_w + (size_t)h * 512 + (kc * 64 + cp) * 2);
        }
        __syncthreads();

        #pragma unroll 4
        for (int cp2 = 0; cp2 < 64; cp2 += 2) {
            ull w00 = sW[cp2 * 64 + lane];
            ull w01 = sW[cp2 * 64 + 32 + lane];
            ull w10 = sW[(cp2 + 1) * 64 + lane];
            ull w11 = sW[(cp2 + 1) * 64 + 32 + lane];
            #pragma unroll
            for (int i = 0; i < 4; i++) {
                const ulonglong2 x = *(const ulonglong2*)(
                    g_x + (size_t)(row0 + i) * 512 + kc * 128 + cp2 * 2);
                fma2(acc[i][0], x.x, w00);
                fma2(acc[i][1], x.x, w01);
                fma2(acc[i][0], x.y, w10);
                fma2(acc[i][1], x.y, w11);
            }
        }
    }

    float b0 = fc_b[lane], b1 = fc_b[32 + lane];
    #pragma unroll
    for (int i = 0; i < 4; i++) {
        int r = row0 + i;
        if (r < Bn) {
            out[(size_t)r * 64 + lane]      = hsum(acc[i][0]) + b0;
            out[(size_t)r * 64 + 32 + lane] = hsum(acc[i][1]) + b1;
        }
    }
}

// ---------------------------------------------------------------------------
extern "C" void kernel_launch(void* const* d_in, const int* in_sizes, int n_in,
                              void* d_out, int out_size) {
    const int*   data        = (const int*)  d_in[0];
    const float* user_sim    = (const float*)d_in[1];
    const float* service_sim = (const float*)d_in[2];
    const float* user_emb    = (const float*)d_in[3];
    const float* service_emb = (const float*)d_in[4];
    const float* cnn_w       = (const float*)d_in[5];
    const float* cnn_b       = (const float*)d_in[6];
    const float* scnn_w      = (const float*)d_in[7];
    const float* scnn_b      = (const float*)d_in[8];
    const float* wi          = (const float*)d_in[9];
    const float* bi          = (const float*)d_in[10];
    const float* wf          = (const float*)d_in[11];
    const float* bf          = (const float*)d_in[12];
    const float* fc_w        = (const float*)d_in[13];
    const float* fc_b        = (const float*)d_in[14];
    float* out = (float*)d_out;

    int Bn = in_sizes[0] / 3;   // 16384

    // 0: one memset clears flags AND counters; fused prep (wT + mark)
    void* flagPtr = nullptr;
    cudaGetSymbolAddress(&flagPtr, g_flagi);
    cudaMemsetAsync(flagPtr, 0, (2 * UE + 2) * sizeof(int), 0);
    prepmark_kernel<<<32 + (Bn + 255) / 256, 256>>>(wf, wi, data, Bn);

    // A: top-32 of both sim matrices (two warps per used row)
    topk_kernel<<<(2 * UE) / 4, 256>>>(user_sim, service_sim);

    // B: per-entity conv (dense warps over used entities)
    conv_kernel<<<(2 * UE) / 8, 256>>>(user_emb, service_emb,
                                       cnn_w, cnn_b, scnn_w, scnn_b);

    // C: projection tables — 4th kernel launch = ncu capture slot next round
    dim3 pg((UE + 31) / 32, 4, 2);
    proj_kernel<<<pg, 256>>>(user_emb, service_emb);

    // D1: per-element fuse + select -> packed x
    pack_kernel<<<(Bn + 7) / 8, 256>>>(data, user_emb, service_emb, bi, bf, Bn);

    // D2: fc GEMM
    fc_kernel<<<(Bn + 31) / 32, 256>>>(fc_w, fc_b, out, Bn);
}

// round 14
// speedup vs baseline: 1.1715x; 1.1715x over previous
#include <cuda_runtime.h>
#include <cuda_bf16.h>
#include <float.h>

#define UE   10000
#define HD   128
#define KSEL 32
#define FULLM 0xffffffffu

// ---------------- scratch (device globals; no runtime allocation) ----------
__device__ int   g_umap[UE * KSEL];
__device__ int   g_smap[UE * KSEL];
__device__ float g_cu[UE * HD];          // conv output per user
__device__ float g_ds[UE * HD];          // conv output per service
// projections: [src 0=a(u),1=c(u),2=b(s),3=d(s)][entity][0:128 wf-proj | 128:256 wi-proj]
__device__ float g_proj[4 * UE * 256];
// packed selected features per batch element (row-major 16384 x 512)
__device__ float g_x[16384 * 512];
// dedup flags + compact used-entity lists; counters live in the tail
// [0:UE) user flags, [UE:2UE) service flags, [2UE]=user count, [2UE+1]=service count
__device__ int g_flagi[2 * UE + 2];
__device__ int g_ulist[UE];
__device__ int g_slist[UE];
// pre-transposed weights: [z][cp2][h] as float4 = W[h][4cp2 .. 4cp2+3]
__device__ float4 g_wT[2 * 32 * 128];

typedef unsigned long long ull;

__device__ __forceinline__ void fma2(ull& d, ull a, ull b) {
    asm("fma.rn.f32x2 %0, %1, %2, %0;" : "+l"(d) : "l"(a), "l"(b));
}
__device__ __forceinline__ ull dupf(float x) {
    unsigned xi = __float_as_uint(x);
    ull r; asm("mov.b64 %0, {%1, %1};" : "=l"(r) : "r"(xi));
    return r;
}
__device__ __forceinline__ float hsum(ull a) {
    unsigned lo, hi;
    asm("mov.b64 {%0, %1}, %2;" : "=r"(lo), "=r"(hi) : "l"(a));
    return __uint_as_float(lo) + __uint_as_float(hi);
}

// ---------------------------------------------------------------------------
// Kernel 0: fused prep. Blocks 0-31: transpose W into g_wT. Blocks 32+:
// mark used entities + build compact lists (g_flagi zeroed by memset).
// ---------------------------------------------------------------------------
__global__ void prepmark_kernel(const float* __restrict__ wf,
                                const float* __restrict__ wi,
                                const int* __restrict__ data, int Bn) {
    int b = blockIdx.x, tid = threadIdx.x;
    if (b < 32) {
        int idx = b * 256 + tid;               // < 8192
        int z   = idx >> 12;
        int cp2 = (idx >> 7) & 31;
        int h   = idx & 127;
        const float* W = z ? wi : wf;
        g_wT[idx] = *(const float4*)(W + h * HD + cp2 * 4);
    } else {
        int i = (b - 32) * 256 + tid;
        if (i >= Bn) return;
        int uid = data[i * 3 + 1];
        int sid = data[i * 3 + 2];
        if (atomicExch(&g_flagi[uid], 1) == 0) {
            int p = atomicAdd(&g_flagi[2 * UE], 1);
            g_ulist[p] = uid;
        }
        if (atomicExch(&g_flagi[UE + sid], 1) == 0) {
            int p = atomicAdd(&g_flagi[2 * UE + 1], 1);
            g_slist[p] = sid;
        }
    }
}

// ---------------------------------------------------------------------------
// Kernel A v4 (R12-proven): per-row top-32 (value desc), index-sorted output.
// One warp per used row. MLP=4 loads; lane-max gate ballot per 128-float
// sub-tile; on trigger, per-component candidate ballots -> ONE shfl per
// candidate + 9-issue sorted insert; thr refreshed once per component
// (stale candidates are rank-correct no-op inserts: pos==32 -> no change).
// ---------------------------------------------------------------------------
__global__ void __launch_bounds__(256) topk_kernel(
        const float* __restrict__ user_sim,
        const float* __restrict__ service_sim) {
    int gw   = (blockIdx.x * blockDim.x + threadIdx.x) >> 5;
    int lane = threadIdx.x & 31;
    if (gw >= 2 * UE) return;

    const float* row;
    int* outp;
    if (gw < UE) {
        if (gw >= g_flagi[2 * UE]) return;
        int rid = g_ulist[gw];
        row = user_sim + (size_t)rid * UE;
        outp = g_umap + rid * KSEL;
    } else {
        int sg = gw - UE;
        if (sg >= g_flagi[2 * UE + 1]) return;
        int rid = g_slist[sg];
        row = service_sim + (size_t)rid * UE;
        outp = g_smap + rid * KSEL;
    }

    const float4* row4 = (const float4*)row;
    const int T4 = UE / 4;                  // 2500 float4 per row

    float lv = -FLT_MAX;   // list value at rank = lane (descending)
    int   li = 0;
    float thr = -FLT_MAX;  // rank-31 value, refreshed per component block

    #pragma unroll 1
    for (int it = 0; it < 20; it++) {       // 20 x 512 floats per warp
        int i0 = it * 128 + lane;
        float4 f[4];
        #pragma unroll
        for (int k = 0; k < 4; k++) {
            int i = i0 + 32 * k;
            if (i < T4) f[k] = __ldcs(row4 + i);
            else        f[k] = make_float4(-FLT_MAX, -FLT_MAX, -FLT_MAX, -FLT_MAX);
        }
        #pragma unroll
        for (int k = 0; k < 4; k++) {
            float m = fmaxf(fmaxf(f[k].x, f[k].y), fmaxf(f[k].z, f[k].w));
            if (__ballot_sync(FULLM, m > thr) == 0) continue;  // warp-uniform
            int base = (it * 128 + 32 * k) * 4;
            float comps[4] = {f[k].x, f[k].y, f[k].z, f[k].w};
            #pragma unroll
            for (int t = 0; t < 4; t++) {
                unsigned ct = __ballot_sync(FULLM, comps[t] > thr);
                while (ct) {
                    int src = __ffs(ct) - 1;
                    ct &= ct - 1;
                    float v = __shfl_sync(FULLM, comps[t], src);
                    // sorted insert vs LIVE list; stale-thr candidates get
                    // pos==32 -> no lane matches -> no-op (rank-correct)
                    unsigned ge = __ballot_sync(FULLM, lv >= v);
                    int pos = __popc(ge);
                    float slv = __shfl_up_sync(FULLM, lv, 1);
                    int   sli = __shfl_up_sync(FULLM, li, 1);
                    if (lane > pos)       { lv = slv; li = sli; }
                    else if (lane == pos) { lv = v;   li = base + src * 4 + t; }
                }
                thr = __shfl_sync(FULLM, lv, 31);   // refresh once per component
            }
        }
    }

    // bitonic sort of the 32 indices ascending
    #pragma unroll
    for (int k = 2; k <= 32; k <<= 1) {
        #pragma unroll
        for (int j = k >> 1; j > 0; j >>= 1) {
            int partner = __shfl_xor_sync(FULLM, li, j);
            bool up    = ((lane & k) == 0);
            bool small = ((lane & j) == 0);
            int mn = min(li, partner), mx = max(li, partner);
            li = (up == small) ? mn : mx;
        }
    }
    outp[lane] = li;
}

// ---------------------------------------------------------------------------
// Kernel B: per-entity 32x7 conv over gathered neighbor embeddings.
// One warp per used entity (dense via compact lists).  (R8-proven version.)
// ---------------------------------------------------------------------------
__global__ void conv_kernel(const float* __restrict__ user_emb,
                            const float* __restrict__ service_emb,
                            const float* __restrict__ cnn_w,
                            const float* __restrict__ cnn_b,
                            const float* __restrict__ scnn_w,
                            const float* __restrict__ scnn_b) {
    __shared__ float sw[224];
    __shared__ float sb;
    int e0 = blockIdx.x * 8;           // 8 warps per CTA; sides split at CTA 1250
    bool user = (e0 < UE);
    const float* emb  = user ? user_emb : service_emb;
    const int*   map  = user ? g_umap   : g_smap;
    float*       outc = user ? g_cu     : g_ds;
    const float* wsrc = user ? cnn_w    : scnn_w;
    if (threadIdx.x < 224) sw[threadIdx.x] = wsrc[threadIdx.x];
    if (threadIdx.x == 0)  sb = (user ? cnn_b : scnn_b)[0];
    __syncthreads();

    int warp = threadIdx.x >> 5, lane = threadIdx.x & 31;
    int widx = e0 + warp;
    int el;
    if (user) {
        if (widx >= g_flagi[2 * UE]) return;
        el = g_ulist[widx];
    } else {
        int sg = widx - UE;
        if (sg >= g_flagi[2 * UE + 1]) return;
        el = g_slist[sg];
    }

    int mk = map[el * KSEL + lane];    // lane holds neighbor index #lane

    float m[7][4];
    #pragma unroll
    for (int t = 0; t < 7; t++)
        m[t][0] = m[t][1] = m[t][2] = m[t][3] = 0.f;

    for (int k = 0; k < 32; k++) {
        int nb = __shfl_sync(FULLM, mk, k);
        float4 x = *(const float4*)(emb + (size_t)nb * HD + lane * 4);
        #pragma unroll
        for (int t = 0; t < 7; t++) {
            float w = sw[k * 7 + t];
            m[t][0] = fmaf(x.x, w, m[t][0]);
            m[t][1] = fmaf(x.y, w, m[t][1]);
            m[t][2] = fmaf(x.z, w, m[t][2]);
            m[t][3] = fmaf(x.w, w, m[t][3]);
        }
    }

    float acc[4] = {sb, sb, sb, sb};
    #pragma unroll
    for (int t = 0; t < 7; t++) {
        float up[4], dn[4];
        #pragma unroll
        for (int j = 0; j < 4; j++) up[j] = __shfl_up_sync(FULLM, m[t][j], 1);
        #pragma unroll
        for (int j = 0; j < 4; j++) dn[j] = __shfl_down_sync(FULLM, m[t][j], 1);
        if (lane == 0)  { up[0] = up[1] = up[2] = up[3] = 0.f; }
        if (lane == 31) { dn[0] = dn[1] = dn[2] = dn[3] = 0.f; }
        const int d = t - 3;
        #pragma unroll
        for (int i = 0; i < 4; i++) {
            const int q = i + d;
            float v = (q < 0) ? up[q + 4] : ((q > 3) ? dn[q - 4] : m[t][q]);
            acc[i] += v;
        }
    }
    float4 o = make_float4(acc[0], acc[1], acc[2], acc[3]);
    *(float4*)(outc + (size_t)el * HD + lane * 4) = o;
}

// ---------------------------------------------------------------------------
// Kernel C v3: projection GEMM over USED entities only, BOTH weight matrices
// per CTA. Tile: 32 rows x 128 h (256 thr); warp = 8 rows x 64 h. sX staged
// ONCE, then z in {wf, wi} computed sequentially from the same tile.
// W via coalesced LDG.128 from g_wT (L1-resident); acc in f32x2.
// ---------------------------------------------------------------------------
__global__ void __launch_bounds__(256, 4) proj_kernel(
        const float* __restrict__ user_emb,
        const float* __restrict__ service_emb) {
    __shared__ float sX[32 * 128];    // 16 KB
    __shared__ int   sRid[32];

    int srcsel = blockIdx.y;          // 0=a(u emb),1=c(u conv),2=b(s emb),3=d(s conv)
    bool userSide = (srcsel < 2);
    int cnt = userSide ? g_flagi[2 * UE] : g_flagi[2 * UE + 1];
    int row0 = blockIdx.x * 32;
    if (row0 >= cnt) return;
    const int* list = userSide ? g_ulist : g_slist;
    const float* X;
    switch (srcsel) {
        case 0:  X = user_emb;    break;
        case 1:  X = g_cu;        break;
        case 2:  X = service_emb; break;
        default: X = g_ds;        break;
    }

    int tid = threadIdx.x;
    if (tid < 32) sRid[tid] = (row0 + tid < cnt) ? list[row0 + tid] : -1;
    __syncthreads();   // sRid visible for staging below

    // stage 32 rows x 128 c (gathered); zero-fill beyond count
    for (int idx = tid; idx < 1024; idx += 256) {
        int r = idx >> 5, c4 = idx & 31;
        int eid = sRid[r];
        float4 v = (eid >= 0) ? *(const float4*)(X + (size_t)eid * HD + c4 * 4)
                              : make_float4(0.f, 0.f, 0.f, 0.f);
        *(float4*)(sX + r * HD + c4 * 4) = v;
    }
    __syncthreads();

    int lane = tid & 31, warp = tid >> 5;
    int rg   = warp & 3;              // row group: rows rg*8 .. rg*8+7
    int hcol = warp >> 2;             // h block: hcol*64 + {0,32} + lane
    const float* xbase = sX + rg * 8 * HD;

    #pragma unroll 1
    for (int z = 0; z < 2; z++) {
        const float4* wbase = g_wT + (z * 32 * 128) + hcol * 64 + lane;
        ull acc[8][2] = {};

        #pragma unroll 4
        for (int cp2 = 0; cp2 < 32; cp2++) {
            float4 w0f = __ldg(wbase + cp2 * 128);
            float4 w1f = __ldg(wbase + cp2 * 128 + 32);
            ull w0x, w0y, w1x, w1y;
            asm("mov.b64 %0, {%1, %2};" : "=l"(w0x) : "f"(w0f.x), "f"(w0f.y));
            asm("mov.b64 %0, {%1, %2};" : "=l"(w0y) : "f"(w0f.z), "f"(w0f.w));
            asm("mov.b64 %0, {%1, %2};" : "=l"(w1x) : "f"(w1f.x), "f"(w1f.y));
            asm("mov.b64 %0, {%1, %2};" : "=l"(w1y) : "f"(w1f.z), "f"(w1f.w));
            #pragma unroll
            for (int i = 0; i < 8; i++) {
                const ulonglong2 x = *(const ulonglong2*)(xbase + i * HD + cp2 * 4);
                fma2(acc[i][0], x.x, w0x);
                fma2(acc[i][0], x.y, w0y);
                fma2(acc[i][1], x.x, w1x);
                fma2(acc[i][1], x.y, w1y);
            }
        }

        #pragma unroll
        for (int i = 0; i < 8; i++) {
            int eid = sRid[rg * 8 + i];
            if (eid >= 0) {
                float* dst = g_proj + (size_t)(srcsel * UE + eid) * 256 + z * 128
                           + hcol * 64 + lane;
                dst[0]  = hsum(acc[i][0]);
                dst[32] = hsum(acc[i][1]);
            }
        }
    }
}

// ---------------------------------------------------------------------------
// Kernel D1: per-batch-element pairs + sigmoid gate + top4-by-norm; writes
// the packed 512-float selected vector to g_x. One warp per element.
// ---------------------------------------------------------------------------
__device__ __forceinline__ float pair_compute(float4 fx, float4 fy,
                                              float4 pxf, float4 pyf,
                                              float4 pxi, float4 pyi,
                                              float4 vbf, float4 vbi,
                                              float* dst, int lane) {
    float s[4]  = {fx.x + fy.x, fx.y + fy.y, fx.z + fy.z, fx.w + fy.w};
    float zf[4] = {pxf.x + pyf.x + vbf.x, pxf.y + pyf.y + vbf.y,
                   pxf.z + pyf.z + vbf.z, pxf.w + pyf.w + vbf.w};
    float zi[4] = {pxi.x + pyi.x + vbi.x, pxi.y + pyi.y + vbi.y,
                   pxi.z + pyi.z + vbi.z, pxi.w + pyi.w + vbi.w};
    float tv[4];
    float n2 = 0.f;
    #pragma unroll
    for (int c = 0; c < 4; c++) {
        float f = 1.f / (1.f + __expf(-zf[c]));
        float v = fmaf(f, zi[c] - s[c], s[c]);   // f*t + (1-f)*s
        v = fmaxf(v, 0.f);
        tv[c] = v;
        n2 = fmaf(v, v, n2);
    }
    *(float4*)(dst + lane * 4) = make_float4(tv[0], tv[1], tv[2], tv[3]);
    #pragma unroll
    for (int o = 16; o > 0; o >>= 1) n2 += __shfl_xor_sync(FULLM, n2, o);
    return n2;
}

__global__ void __launch_bounds__(256) pack_kernel(
        const int* __restrict__ data,
        const float* __restrict__ user_emb,
        const float* __restrict__ service_emb,
        const float* __restrict__ bi,
        const float* __restrict__ bf,
        int Bn) {
    __shared__ float wbuf[8 * 768];   // 8 warps * 6 pairs * 128

    int tid = threadIdx.x;
    int warp = tid >> 5, lane = tid & 31;
    int b = blockIdx.x * 8 + warp;
    if (b >= Bn) return;
    float* mybuf = wbuf + warp * 768;

    int uid = data[b * 3 + 1];
    int sid = data[b * 3 + 2];

    float4 fa  = *(const float4*)(user_emb    + (size_t)uid * HD + lane * 4);
    float4 fb  = *(const float4*)(service_emb + (size_t)sid * HD + lane * 4);
    float4 fc4 = *(const float4*)(g_cu + (size_t)uid * HD + lane * 4);
    float4 fd  = *(const float4*)(g_ds + (size_t)sid * HD + lane * 4);

    const float* pA = g_proj + (size_t)(0 * UE + uid) * 256;
    const float* pC = g_proj + (size_t)(1 * UE + uid) * 256;
    const float* pB = g_proj + (size_t)(2 * UE + sid) * 256;
    const float* pD = g_proj + (size_t)(3 * UE + sid) * 256;
    float4 aF = *(const float4*)(pA + lane * 4);
    float4 aI = *(const float4*)(pA + 128 + lane * 4);
    float4 cF = *(const float4*)(pC + lane * 4);
    float4 cI = *(const float4*)(pC + 128 + lane * 4);
    float4 bF = *(const float4*)(pB + lane * 4);
    float4 bI = *(const float4*)(pB + 128 + lane * 4);
    float4 dF = *(const float4*)(pD + lane * 4);
    float4 dI = *(const float4*)(pD + 128 + lane * 4);

    float4 vbf = *(const float4*)(bf + lane * 4);
    float4 vbi = *(const float4*)(bi + lane * 4);

    float norms[6];
    norms[0] = pair_compute(fa,  fb,  aF, bF, aI, bI, vbf, vbi, mybuf + 0 * 128, lane); // a+b
    norms[1] = pair_compute(fa,  fc4, aF, cF, aI, cI, vbf, vbi, mybuf + 1 * 128, lane); // a+c
    norms[2] = pair_compute(fa,  fd,  aF, dF, aI, dI, vbf, vbi, mybuf + 2 * 128, lane); // a+d
    norms[3] = pair_compute(fb,  fc4, bF, cF, bI, cI, vbf, vbi, mybuf + 3 * 128, lane); // b+c
    norms[4] = pair_compute(fb,  fd,  bF, dF, bI, dI, vbf, vbi, mybuf + 4 * 128, lane); // b+d
    norms[5] = pair_compute(fc4, fd,  cF, dF, cI, dI, vbf, vbi, mybuf + 5 * 128, lane); // c+d

    // top-4 by norm (desc), ties -> lower index (strict >, ascending scan)
    int ord[4];
    unsigned usedm = 0;
    #pragma unroll
    for (int r = 0; r < 4; r++) {
        int best = 0; float bv = -1.f;
        #pragma unroll
        for (int p = 0; p < 6; p++) {
            bool ok = !((usedm >> p) & 1u) && (norms[p] > bv);
            if (ok) { bv = norms[p]; best = p; }
        }
        ord[r] = best;
        usedm |= (1u << best);
    }
    __syncwarp();

    float* xdst = g_x + (size_t)b * 512;
    #pragma unroll
    for (int r = 0; r < 4; r++) {
        float4 v = *(const float4*)(mybuf + ord[r] * 128 + lane * 4);
        *(float4*)(xdst + r * 128 + lane * 4) = v;
    }
}

// ---------------------------------------------------------------------------
// Kernel D2: fc GEMM. out[16384 x 64] = g_x[16384 x 512] @ fc_w.T + fc_b.
// ---------------------------------------------------------------------------
__global__ void __launch_bounds__(256) fc_kernel(
        const float* __restrict__ fc_w,
        const float* __restrict__ fc_b,
        float* __restrict__ out, int Bn) {
    __shared__ ull sW[64 * 64];   // 32 KB: chunk of 64 c-pairs x 64 h

    int tid = threadIdx.x, lane = tid & 31, warp = tid >> 5;
    int row0 = blockIdx.x * 32 + warp * 4;

    ull acc[4][2] = {};

    #pragma unroll 1
    for (int kc = 0; kc < 4; kc++) {
        __syncthreads();
        for (int idx = tid; idx < 4096; idx += 256) {
            int cp = idx >> 6, h = idx & 63;
            sW[cp * 64 + h] = *(const ull*)(fc_w + (size_t)h * 512 + (kc * 64 + cp) * 2);
        }
        __syncthreads();

        #pragma unroll 4
        for (int cp2 = 0; cp2 < 64; cp2 += 2) {
            ull w00 = sW[cp2 * 64 + lane];
            ull w01 = sW[cp2 * 64 + 32 + lane];
            ull w10 = sW[(cp2 + 1) * 64 + lane];
            ull w11 = sW[(cp2 + 1) * 64 + 32 + lane];
            #pragma unroll
            for (int i = 0; i < 4; i++) {
                const ulonglong2 x = *(const ulonglong2*)(
                    g_x + (size_t)(row0 + i) * 512 + kc * 128 + cp2 * 2);
                fma2(acc[i][0], x.x, w00);
                fma2(acc[i][1], x.x, w01);
                fma2(acc[i][0], x.y, w10);
                fma2(acc[i][1], x.y, w11);
            }
        }
    }

    float b0 = fc_b[lane], b1 = fc_b[32 + lane];
    #pragma unroll
    for (int i = 0; i < 4; i++) {
        int r = row0 + i;
        if (r < Bn) {
            out[(size_t)r * 64 + lane]      = hsum(acc[i][0]) + b0;
            out[(size_t)r * 64 + 32 + lane] = hsum(acc[i][1]) + b1;
        }
    }
}

// ---------------------------------------------------------------------------
extern "C" void kernel_launch(void* const* d_in, const int* in_sizes, int n_in,
                              void* d_out, int out_size) {
    const int*   data        = (const int*)  d_in[0];
    const float* user_sim    = (const float*)d_in[1];
    const float* service_sim = (const float*)d_in[2];
    const float* user_emb    = (const float*)d_in[3];
    const float* service_emb = (const float*)d_in[4];
    const float* cnn_w       = (const float*)d_in[5];
    const float* cnn_b       = (const float*)d_in[6];
    const float* scnn_w      = (const float*)d_in[7];
    const float* scnn_b      = (const float*)d_in[8];
    const float* wi          = (const float*)d_in[9];
    const float* bi          = (const float*)d_in[10];
    const float* wf          = (const float*)d_in[11];
    const float* bf          = (const float*)d_in[12];
    const float* fc_w        = (const float*)d_in[13];
    const float* fc_b        = (const float*)d_in[14];
    float* out = (float*)d_out;

    int Bn = in_sizes[0] / 3;   // 16384

    // 0: one memset clears flags AND counters; fused prep (wT + mark)
    void* flagPtr = nullptr;
    cudaGetSymbolAddress(&flagPtr, g_flagi);
    cudaMemsetAsync(flagPtr, 0, (2 * UE + 2) * sizeof(int), 0);
    prepmark_kernel<<<32 + (Bn + 255) / 256, 256>>>(wf, wi, data, Bn);

    // A: top-32 of both sim matrices (one warp per used row, R12 exact)
    topk_kernel<<<(2 * UE) / 8, 256>>>(user_sim, service_sim);

    // B: per-entity conv (dense warps over used entities)
    conv_kernel<<<(2 * UE) / 8, 256>>>(user_emb, service_emb,
                                       cnn_w, cnn_b, scnn_w, scnn_b);

    // C: projection tables — both z per CTA; 4th launch = ncu capture slot
    dim3 pg((UE + 31) / 32, 4);
    proj_kernel<<<pg, 256>>>(user_emb, service_emb);

    // D1: per-element fuse + select -> packed x
    pack_kernel<<<(Bn + 7) / 8, 256>>>(data, user_emb, service_emb, bi, bf, Bn);

    // D2: fc GEMM
    fc_kernel<<<(Bn + 31) / 32, 256>>>(fc_w, fc_b, out, Bn);
}